// round 15
// baseline (speedup 1.0000x reference)
#include <cuda_runtime.h>
#include <cuda_bf16.h>
#include <math.h>

#define N_      4096
#define E_      4096
#define NHID_   512
#define NHEAD_  8
#define DK_     64
#define NLAYER_ 4
#define NCLASS_ 16
#define CAP_    256
#define L2E_    1.4426950408889634f

// ---------------- device scratch (static, no allocation) ----------------
__device__ unsigned g_HB [(size_t)N_ * (E_ / 32)];   // 2 MB node-major bitmask
__device__ unsigned g_HBT[(size_t)E_ * (N_ / 32)];   // 2 MB edge-major bitmask
__device__ float g_U  [(size_t)E_ * NHID_];
__device__ float g_x  [N_ * NHID_];
__device__ __nv_bfloat16 g_q [N_ * NHID_];
__device__ __nv_bfloat16 g_k [N_ * NHID_];
__device__ float g_v  [N_ * NHID_];
__device__ __nv_bfloat16 g_vt[(size_t)NHEAD_ * DK_ * N_];
__device__ float g_ctx[N_ * NHID_];
__device__ float g_tmp[N_ * NHID_];
__device__ float g_dv2[N_];
__device__ float g_dei[E_];
__device__ int   g_adjN[(size_t)N_ * CAP_];
__device__ int   g_adjE[(size_t)E_ * CAP_];
__device__ int   g_degN[N_];
__device__ int   g_degE[E_];
__device__ __nv_bfloat16 g_wtF[NHID_ * NHID_];
__device__ __nv_bfloat16 g_wtQ[NLAYER_ * NHID_ * NHID_];
__device__ __nv_bfloat16 g_wtK[NLAYER_ * NHID_ * NHID_];
__device__ __nv_bfloat16 g_wtV[NLAYER_ * NHID_ * NHID_];
__device__ __nv_bfloat16 g_wtO[NLAYER_ * NHID_ * NHID_];

// ---------------- helpers ----------------
__device__ __forceinline__ void mma_bf16(
    float& d0, float& d1, float& d2, float& d3,
    unsigned a0, unsigned a1, unsigned a2, unsigned a3,
    unsigned b0, unsigned b1)
{
    asm volatile(
        "mma.sync.aligned.m16n8k16.row.col.f32.bf16.bf16.f32 "
        "{%0,%1,%2,%3}, {%4,%5,%6,%7}, {%8,%9}, {%0,%1,%2,%3};"
        : "+f"(d0), "+f"(d1), "+f"(d2), "+f"(d3)
        : "r"(a0), "r"(a1), "r"(a2), "r"(a3), "r"(b0), "r"(b1));
}
__device__ __forceinline__ unsigned pack_bf16(float x, float y) {
    __nv_bfloat162 v = __floats2bfloat162_rn(x, y);
    return *(unsigned*)&v;
}
__device__ __forceinline__ uint4 pack8(float4 a, float4 b) {
    uint4 o;
    o.x = pack_bf16(a.x, a.y); o.y = pack_bf16(a.z, a.w);
    o.z = pack_bf16(b.x, b.y); o.w = pack_bf16(b.z, b.w);
    return o;
}
#define CP_ASYNC16(dst, src) \
    asm volatile("cp.async.ca.shared.global [%0], [%1], 16;" :: "r"(dst), "l"(src))
#define CP_COMMIT() asm volatile("cp.async.commit_group;")
#define CP_WAIT(n)  asm volatile("cp.async.wait_group %0;" :: "n"(n))

// ---------------- setup: node pass (reads H once, emits bits + node adjacency) ----------------
__global__ __launch_bounds__(256) void build_node_kernel(const float* __restrict__ H) {
    const int row = blockIdx.x, tid = threadIdx.x;
    const int w = tid >> 5, lane = tid & 31;
    const float* r = H + (size_t)row * E_;
    __shared__ unsigned bits[128];
    __shared__ int sc[128];

    #pragma unroll
    for (int i = 0; i < 16; i++) {
        int chunk = w * 16 + i;
        float v = r[chunk * 32 + lane];
        unsigned m = __ballot_sync(0xffffffffu, v != 0.f);
        if (lane == 0) {
            bits[chunk] = m;
            sc[chunk] = __popc(m);
            g_HB[(size_t)row * 128 + chunk] = m;
        }
    }
    __syncthreads();

    for (int off = 1; off < 128; off <<= 1) {
        int v = (tid < 128 && tid >= off) ? sc[tid - off] : 0;
        __syncthreads();
        if (tid < 128) sc[tid] += v;
        __syncthreads();
    }

    #pragma unroll
    for (int i = 0; i < 16; i++) {
        int chunk = w * 16 + i;
        unsigned m = bits[chunk];
        int base = (chunk > 0) ? sc[chunk - 1] : 0;
        int rank = __popc(m & ((1u << lane) - 1u));
        if ((m >> lane) & 1u) {
            int pos = base + rank;
            if (pos < CAP_) g_adjN[(size_t)row * CAP_ + pos] = chunk * 32 + lane;
        }
    }
    if (tid == 0) {
        int full = sc[127];
        g_degN[row] = min(full, CAP_);
        g_dv2[row] = (row == 0) ? 1.0f : rsqrtf((float)full);
    }
}

// ---------------- setup: 32x32 bit transpose HB -> HBT ----------------
__global__ __launch_bounds__(256) void bittrans_kernel() {
    const int w = threadIdx.x >> 5, lane = threadIdx.x & 31;
    const int wn = blockIdx.y * 8 + w;       // node word index (0..127)
    const int e0 = blockIdx.x * 32;          // edge block
    const int n0 = wn * 32;
    unsigned wordrow = g_HB[(size_t)(n0 + lane) * 128 + blockIdx.x];
    #pragma unroll
    for (int j = 0; j < 32; j++) {
        unsigned col = __ballot_sync(0xffffffffu, (wordrow >> j) & 1u);
        if (lane == j) g_HBT[(size_t)(e0 + j) * 128 + wn] = col;
    }
}

// ---------------- setup: edge pass from HBT ----------------
__global__ __launch_bounds__(128) void build_edge_kernel() {
    const int e = blockIdx.x, t = threadIdx.x;
    unsigned m = g_HBT[(size_t)e * 128 + t];
    __shared__ int sc[128];
    sc[t] = __popc(m);
    __syncthreads();
    for (int off = 1; off < 128; off <<= 1) {
        int v = (t >= off) ? sc[t - off] : 0;
        __syncthreads();
        sc[t] += v;
        __syncthreads();
    }
    int pos = (t > 0) ? sc[t - 1] : 0;
    unsigned mm = m;
    while (mm) {
        int b = __ffs(mm) - 1;
        mm &= mm - 1;
        if (pos < CAP_) g_adjE[(size_t)e * CAP_ + pos] = t * 32 + b;
        pos++;
    }
    if (t == 127) {
        int full = sc[127];
        g_degE[e] = min(full, CAP_);
        g_dei[e] = 1.0f / (float)full;
    }
}

// ---------------- all weight transposes in one launch ----------------
__global__ void wtrans_all_kernel(const float* __restrict__ w_feat,
                                  const float* __restrict__ Wq, const float* __restrict__ Wk,
                                  const float* __restrict__ Wv, const float* __restrict__ Wo)
{
    __shared__ float tile[32][33];
    const int z = blockIdx.z;
    const float* W;
    __nv_bfloat16* out;
    if (z == 0) { W = w_feat; out = g_wtF; }
    else {
        int which = (z - 1) >> 2, layer = (z - 1) & 3;
        size_t off = (size_t)layer * NHID_ * NHID_;
        W   = (which == 0) ? Wq : (which == 1) ? Wk : (which == 2) ? Wv : Wo;
        out = (which == 0) ? g_wtQ : (which == 1) ? g_wtK : (which == 2) ? g_wtV : g_wtO;
        W += off; out += off;
    }
    int bx = blockIdx.x * 32, by = blockIdx.y * 32;
    int tx = threadIdx.x, ty = threadIdx.y;
    #pragma unroll
    for (int i = 0; i < 32; i += 8)
        tile[ty + i][tx] = W[(size_t)(by + ty + i) * NHID_ + bx + tx];
    __syncthreads();
    #pragma unroll
    for (int i = 0; i < 32; i += 8)
        out[(size_t)(bx + ty + i) * NHID_ + by + tx] = __float2bfloat16(tile[tx][ty + i]);
}

// ---------------- bf16 tensor-core GEMM (64x128, 256 thr) ----------------
__global__ __launch_bounds__(256, 2) void gemm_bf16_kernel(
    const float* __restrict__ A,
    const __nv_bfloat16* __restrict__ B0t, const __nv_bfloat16* __restrict__ B1t,
    const __nv_bfloat16* __restrict__ B2t,
    void* __restrict__ C0v, void* __restrict__ C1v, void* __restrict__ C2v,
    const float* __restrict__ bias0, const float* __restrict__ bias1, const float* __restrict__ bias2,
    int m0_, int m1_, int m2_)
{
    constexpr int BM = 64, BN = 128, BK = 32, KK = NHID_;
    constexpr int SW = 20;
    __shared__ __align__(16) unsigned As[2][BM][SW];
    __shared__ __align__(16) unsigned Bs[2][BN][SW];

    const int z = blockIdx.z;
    const __nv_bfloat16* Bt = (z == 0) ? B0t : (z == 1) ? B1t : B2t;
    void* Cv          = (z == 0) ? C0v : (z == 1) ? C1v : C2v;
    const float* bias = (z == 0) ? bias0 : (z == 1) ? bias1 : bias2;
    const int mode    = (z == 0) ? m0_ : (z == 1) ? m1_ : m2_;

    const int bm = blockIdx.y * BM, bn = blockIdx.x * BN;
    const int tid = threadIdx.x;
    const int lane = tid & 31, w = tid >> 5;
    const int g = lane >> 2, tg = lane & 3;
    const int m0w = (w & 1) * 32, n0w = (w >> 1) * 32;

    const int ar = tid >> 2, aw4 = (tid & 3) * 4;
    const int br = tid >> 1, bw4 = (tid & 1) * 8;
    const unsigned* Btw = (const unsigned*)Bt;

    float acc[2][4][4];
    #pragma unroll
    for (int mt = 0; mt < 2; mt++)
        #pragma unroll
        for (int nt = 0; nt < 4; nt++)
            #pragma unroll
            for (int j = 0; j < 4; j++) acc[mt][nt][j] = 0.f;

    {
        const float* ap = A + (size_t)(bm + ar) * KK + aw4 * 2;
        float4 a0 = *(const float4*)ap, a1 = *(const float4*)(ap + 4);
        *(uint4*)&As[0][ar][aw4] = pack8(a0, a1);
        const unsigned* bp = Btw + (size_t)(bn + br) * (KK / 2) + bw4;
        *(uint4*)&Bs[0][br][bw4]     = *(const uint4*)bp;
        *(uint4*)&Bs[0][br][bw4 + 4] = *(const uint4*)(bp + 4);
    }
    __syncthreads();

    const int nk = KK / BK;
    for (int t = 0; t < nk; t++) {
        float4 ra0, ra1;
        uint4 rb0, rb1;
        const bool pf = (t + 1 < nk);
        if (pf) {
            const int k0 = (t + 1) * BK;
            const float* ap = A + (size_t)(bm + ar) * KK + k0 + aw4 * 2;
            ra0 = *(const float4*)ap; ra1 = *(const float4*)(ap + 4);
            const unsigned* bp = Btw + (size_t)(bn + br) * (KK / 2) + k0 / 2 + bw4;
            rb0 = *(const uint4*)bp; rb1 = *(const uint4*)(bp + 4);
        }
        const int cur = t & 1;
        #pragma unroll
        for (int s = 0; s < 2; s++) {
            const int kb = s * 8;
            unsigned a[2][4], b[4][2];
            #pragma unroll
            for (int mt = 0; mt < 2; mt++) {
                const unsigned* r0 = &As[cur][m0w + mt * 16 + g][kb + tg];
                const unsigned* r1 = &As[cur][m0w + mt * 16 + g + 8][kb + tg];
                a[mt][0] = r0[0]; a[mt][1] = r1[0]; a[mt][2] = r0[4]; a[mt][3] = r1[4];
            }
            #pragma unroll
            for (int nt = 0; nt < 4; nt++) {
                const unsigned* rb = &Bs[cur][n0w + nt * 8 + g][kb + tg];
                b[nt][0] = rb[0]; b[nt][1] = rb[4];
            }
            #pragma unroll
            for (int mt = 0; mt < 2; mt++)
                #pragma unroll
                for (int nt = 0; nt < 4; nt++)
                    mma_bf16(acc[mt][nt][0], acc[mt][nt][1], acc[mt][nt][2], acc[mt][nt][3],
                             a[mt][0], a[mt][1], a[mt][2], a[mt][3], b[nt][0], b[nt][1]);
        }
        if (pf) {
            const int nxt = cur ^ 1;
            *(uint4*)&As[nxt][ar][aw4] = pack8(ra0, ra1);
            *(uint4*)&Bs[nxt][br][bw4]     = rb0;
            *(uint4*)&Bs[nxt][br][bw4 + 4] = rb1;
        }
        __syncthreads();
    }

    #pragma unroll
    for (int mt = 0; mt < 2; mt++) {
        const int r0 = bm + m0w + mt * 16 + g;
        #pragma unroll
        for (int nt = 0; nt < 4; nt++) {
            const int c = bn + n0w + nt * 8 + 2 * tg;
            float bx = __ldg(&bias[c]), by = __ldg(&bias[c + 1]);
            float v00 = acc[mt][nt][0] + bx, v01 = acc[mt][nt][1] + by;
            float v10 = acc[mt][nt][2] + bx, v11 = acc[mt][nt][3] + by;
            if (mode == 1) {
                __nv_bfloat16* Cb = (__nv_bfloat16*)Cv;
                *(__nv_bfloat162*)(Cb + (size_t)r0 * NHID_ + c) = __floats2bfloat162_rn(v00, v01);
                *(__nv_bfloat162*)(Cb + (size_t)(r0 + 8) * NHID_ + c) = __floats2bfloat162_rn(v10, v11);
            } else {
                float* C = (float*)Cv;
                *(float2*)(C + (size_t)r0 * NHID_ + c) = make_float2(v00, v01);
                *(float2*)(C + (size_t)(r0 + 8) * NHID_ + c) = make_float2(v10, v11);
                if (mode == 2) {
                    g_vt[(size_t)c * N_ + r0]           = __float2bfloat16(v00);
                    g_vt[(size_t)(c + 1) * N_ + r0]     = __float2bfloat16(v01);
                    g_vt[(size_t)c * N_ + r0 + 8]       = __float2bfloat16(v10);
                    g_vt[(size_t)(c + 1) * N_ + r0 + 8] = __float2bfloat16(v11);
                }
            }
        }
    }
}

// ---------------- FA bf16 flash attention (R12: 128 q rows/CTA, cp.async) ----------------
__global__ __launch_bounds__(256, 2) void attn_kernel() {
    __shared__ unsigned Ks[2][64][36];
    __shared__ unsigned Vs[2][64][36];

    const int h = blockIdx.y, qb = blockIdx.x;
    const int tid = threadIdx.x, w = tid >> 5, lane = tid & 31;
    const int g = lane >> 2, tg = lane & 3;
    const int r0 = qb * 128 + w * 16 + g;
    const int lw = tid >> 3, lwd = (tid & 7) * 4, l4 = tid & 7;

    unsigned ks_dst[2][2], vs_dst[2][2];
    #pragma unroll
    for (int bufi = 0; bufi < 2; bufi++)
        #pragma unroll
        for (int i = 0; i < 2; i++) {
            int r = lw + i * 32;
            ks_dst[bufi][i] = (unsigned)__cvta_generic_to_shared(&Ks[bufi][r][lwd]);
            vs_dst[bufi][i] = (unsigned)__cvta_generic_to_shared(&Vs[bufi][r][lwd]);
        }

    unsigned qa[4][4];
    {
        const __nv_bfloat16* Q0 = g_q + (size_t)r0 * NHID_ + h * 64;
        const __nv_bfloat16* Q1 = Q0 + (size_t)8 * NHID_;
        const __nv_bfloat162 s2 = __floats2bfloat162_rn(0.125f, 0.125f);
        #pragma unroll
        for (int ks = 0; ks < 4; ks++) {
            __nv_bfloat162 t;
            t = __hmul2(*(const __nv_bfloat162*)(Q0 + ks * 16 + 2 * tg), s2);
            qa[ks][0] = *(unsigned*)&t;
            t = __hmul2(*(const __nv_bfloat162*)(Q1 + ks * 16 + 2 * tg), s2);
            qa[ks][1] = *(unsigned*)&t;
            t = __hmul2(*(const __nv_bfloat162*)(Q0 + ks * 16 + 8 + 2 * tg), s2);
            qa[ks][2] = *(unsigned*)&t;
            t = __hmul2(*(const __nv_bfloat162*)(Q1 + ks * 16 + 8 + 2 * tg), s2);
            qa[ks][3] = *(unsigned*)&t;
        }
    }

    float ol0 = 0.f, ol1 = 0.f;
    float oacc[8][4];
    #pragma unroll
    for (int nt = 0; nt < 8; nt++)
        #pragma unroll
        for (int j = 0; j < 4; j++) oacc[nt][j] = 0.f;

    #pragma unroll
    for (int i = 0; i < 2; i++) {
        int r = lw + i * 32;
        CP_ASYNC16(ks_dst[0][i], g_k + (size_t)r * NHID_ + h * 64 + l4 * 8);
        CP_ASYNC16(vs_dst[0][i], g_vt + ((size_t)h * 64 + r) * N_ + l4 * 8);
    }
    CP_COMMIT();

    for (int it = 0; it < N_ / 64; it++) {
        const int cur = it & 1;
        const bool pf = (it + 1 < N_ / 64);
        if (pf) {
            const int kvn = (it + 1) * 64;
            const int nxt = cur ^ 1;
            #pragma unroll
            for (int i = 0; i < 2; i++) {
                int r = lw + i * 32;
                CP_ASYNC16(ks_dst[nxt][i], g_k + (size_t)(kvn + r) * NHID_ + h * 64 + l4 * 8);
                CP_ASYNC16(vs_dst[nxt][i], g_vt + ((size_t)h * 64 + r) * N_ + kvn + l4 * 8);
            }
            CP_COMMIT();
            CP_WAIT(1);
        } else {
            CP_WAIT(0);
        }
        __syncthreads();

        float s[8][4];
        #pragma unroll
        for (int nt = 0; nt < 8; nt++)
            #pragma unroll
            for (int j = 0; j < 4; j++) s[nt][j] = 0.f;
        #pragma unroll
        for (int ks = 0; ks < 4; ks++) {
            #pragma unroll
            for (int nt = 0; nt < 8; nt++) {
                unsigned b0 = Ks[cur][g + nt * 8][ks * 8 + tg];
                unsigned b1 = Ks[cur][g + nt * 8][ks * 8 + 4 + tg];
                mma_bf16(s[nt][0], s[nt][1], s[nt][2], s[nt][3],
                         qa[ks][0], qa[ks][1], qa[ks][2], qa[ks][3], b0, b1);
            }
        }

        unsigned pw[8][2];
        #pragma unroll
        for (int nt = 0; nt < 8; nt++) {
            float p0 = exp2f(s[nt][0] * L2E_);
            float p1 = exp2f(s[nt][1] * L2E_);
            float p2 = exp2f(s[nt][2] * L2E_);
            float p3 = exp2f(s[nt][3] * L2E_);
            ol0 += p0 + p1; ol1 += p2 + p3;
            pw[nt][0] = pack_bf16(p0, p1);
            pw[nt][1] = pack_bf16(p2, p3);
        }

        #pragma unroll
        for (int kp = 0; kp < 4; kp++) {
            unsigned a0 = pw[2 * kp][0], a1 = pw[2 * kp][1];
            unsigned a2 = pw[2 * kp + 1][0], a3 = pw[2 * kp + 1][1];
            #pragma unroll
            for (int nt = 0; nt < 8; nt++) {
                unsigned b0 = Vs[cur][g + nt * 8][kp * 8 + tg];
                unsigned b1 = Vs[cur][g + nt * 8][kp * 8 + 4 + tg];
                mma_bf16(oacc[nt][0], oacc[nt][1], oacc[nt][2], oacc[nt][3],
                         a0, a1, a2, a3, b0, b1);
            }
        }
        __syncthreads();
    }

    ol0 += __shfl_xor_sync(0xffffffffu, ol0, 1);
    ol0 += __shfl_xor_sync(0xffffffffu, ol0, 2);
    ol1 += __shfl_xor_sync(0xffffffffu, ol1, 1);
    ol1 += __shfl_xor_sync(0xffffffffu, ol1, 2);

    float inv0 = 0.5f / ol0, inv1 = 0.5f / ol1;
    float* C0 = g_ctx + (size_t)r0 * NHID_ + h * 64;
    float* C1 = C0 + (size_t)8 * NHID_;
    #pragma unroll
    for (int nt = 0; nt < 8; nt++) {
        int c = nt * 8 + 2 * tg;
        *(float2*)(C0 + c) = make_float2(oacc[nt][0] * inv0, oacc[nt][1] * inv0);
        *(float2*)(C1 + c) = make_float2(oacc[nt][2] * inv1, oacc[nt][3] * inv1);
    }
}

// ---------------- sparse G@V pieces ----------------
__global__ __launch_bounds__(128) void edge_gather_kernel() {
    int e = blockIdx.x, tid = threadIdx.x;
    int d = g_degE[e];
    const int* lst = g_adjE + (size_t)e * CAP_;
    float4 acc = make_float4(0.f, 0.f, 0.f, 0.f);
    const float4* V4 = (const float4*)g_v;
    for (int t = 0; t < d; t++) {
        int n = lst[t];
        float w = g_dv2[n];
        float4 v = V4[(size_t)n * (NHID_ / 4) + tid];
        acc.x += w * v.x; acc.y += w * v.y; acc.z += w * v.z; acc.w += w * v.w;
    }
    float de = g_dei[e];
    acc.x *= de; acc.y *= de; acc.z *= de; acc.w *= de;
    ((float4*)g_U)[(size_t)e * (NHID_ / 4) + tid] = acc;
}

__global__ __launch_bounds__(128) void node_scatter_kernel() {
    int n = blockIdx.x, tid = threadIdx.x;
    int d = g_degN[n];
    const int* lst = g_adjN + (size_t)n * CAP_;
    float4 acc = make_float4(0.f, 0.f, 0.f, 0.f);
    const float4* U4 = (const float4*)g_U;
    for (int t = 0; t < d; t++) {
        int e = lst[t];
        float4 u = U4[(size_t)e * (NHID_ / 4) + tid];
        acc.x += u.x; acc.y += u.y; acc.z += u.z; acc.w += u.w;
    }
    float w = 0.5f * g_dv2[n];
    float4* cp = (float4*)g_ctx + (size_t)n * (NHID_ / 4) + tid;
    float4 c = *cp;
    c.x += w * acc.x; c.y += w * acc.y; c.z += w * acc.z; c.w += w * acc.w;
    *cp = c;
}

// ---------------- layernorm + residual + PReLU: warp per row ----------------
__global__ __launch_bounds__(256) void ln_prelu_kernel(
    const float* __restrict__ g, const float* __restrict__ b,
    const float* __restrict__ prelu_a, int layer)
{
    const int w = threadIdx.x >> 5, lane = threadIdx.x & 31;
    const int n = blockIdx.x * 8 + w;
    const size_t base = (size_t)n * NHID_;
    float t[16];
    #pragma unroll
    for (int j = 0; j < 4; j++) {
        int c = j * 128 + lane * 4;
        float4 a = *(const float4*)(g_tmp + base + c);
        float4 x = *(const float4*)(g_x + base + c);
        t[j * 4 + 0] = a.x + x.x; t[j * 4 + 1] = a.y + x.y;
        t[j * 4 + 2] = a.z + x.z; t[j * 4 + 3] = a.w + x.w;
    }
    float s = 0.f;
    #pragma unroll
    for (int i = 0; i < 16; i++) s += t[i];
    #pragma unroll
    for (int o = 16; o > 0; o >>= 1) s += __shfl_xor_sync(0xffffffffu, s, o);
    float mu = s * (1.0f / NHID_);
    float vs = 0.f;
    #pragma unroll
    for (int i = 0; i < 16; i++) { float d = t[i] - mu; vs += d * d; }
    #pragma unroll
    for (int o = 16; o > 0; o >>= 1) vs += __shfl_xor_sync(0xffffffffu, vs, o);
    float rs = rsqrtf(vs * (1.0f / NHID_) + 1e-5f);
    float a = prelu_a[layer];
    #pragma unroll
    for (int j = 0; j < 4; j++) {
        int c = j * 128 + lane * 4;
        float4 gg = *(const float4*)(g + c);
        float4 bb = *(const float4*)(b + c);
        float4 y;
        y.x = (t[j * 4 + 0] - mu) * rs * gg.x + bb.x;
        y.y = (t[j * 4 + 1] - mu) * rs * gg.y + bb.y;
        y.z = (t[j * 4 + 2] - mu) * rs * gg.z + bb.z;
        y.w = (t[j * 4 + 3] - mu) * rs * gg.w + bb.w;
        y.x = (y.x >= 0.f) ? y.x : a * y.x;
        y.y = (y.y >= 0.f) ? y.y : a * y.y;
        y.z = (y.z >= 0.f) ? y.z : a * y.z;
        y.w = (y.w >= 0.f) ? y.w : a * y.w;
        *(float4*)(g_x + base + c) = y;
    }
}

// ---------------- classifier + log_softmax ----------------
__global__ __launch_bounds__(256) void cls_kernel(
    const float* __restrict__ w_cls, const float* __restrict__ b_cls,
    float* __restrict__ out)
{
    int w = threadIdx.x >> 5, lane = threadIdx.x & 31;
    int n = blockIdx.x * 8 + w;
    int half = lane >> 4, c = lane & 15;
    const float* xr = g_x + (size_t)n * NHID_;
    float acc = 0.f;
    #pragma unroll 4
    for (int kk = 0; kk < 256; kk++) {
        int k = half * 256 + kk;
        acc += xr[k] * __ldg(&w_cls[k * NCLASS_ + c]);
    }
    acc += __shfl_xor_sync(0xffffffffu, acc, 16);
    acc += __ldg(&b_cls[c]);
    float mx = acc;
    #pragma unroll
    for (int o = 1; o < 16; o <<= 1) mx = fmaxf(mx, __shfl_xor_sync(0xffffffffu, mx, o));
    float e = expf(acc - mx), s = e;
    #pragma unroll
    for (int o = 1; o < 16; o <<= 1) s += __shfl_xor_sync(0xffffffffu, s, o);
    if (lane < 16) out[(size_t)n * NCLASS_ + c] = acc - mx - logf(s);
}

// ---------------- host ----------------
extern "C" void kernel_launch(void* const* d_in, const int* in_sizes, int n_in,
                              void* d_out, int out_size) {
    const float* X0      = (const float*)d_in[0];
    const float* H       = (const float*)d_in[1];
    const float* w_feat  = (const float*)d_in[2];
    const float* b_feat  = (const float*)d_in[3];
    const float* Wq      = (const float*)d_in[4];
    const float* bq      = (const float*)d_in[5];
    const float* Wk      = (const float*)d_in[6];
    const float* bk      = (const float*)d_in[7];
    const float* Wv      = (const float*)d_in[8];
    const float* bv      = (const float*)d_in[9];
    const float* Wo      = (const float*)d_in[10];
    const float* bo      = (const float*)d_in[11];
    const float* ln_g    = (const float*)d_in[12];
    const float* ln_b    = (const float*)d_in[13];
    const float* prelu_a = (const float*)d_in[14];
    const float* w_cls   = (const float*)d_in[15];
    const float* b_cls   = (const float*)d_in[16];
    float* out = (float*)d_out;

    float *px, *pv, *pctx, *ptmp;
    void *pq, *pk;
    __nv_bfloat16 *pwtF, *pwtQ, *pwtK, *pwtV, *pwtO;
    cudaGetSymbolAddress((void**)&px,    g_x);
    cudaGetSymbolAddress(&pq,            g_q);
    cudaGetSymbolAddress(&pk,            g_k);
    cudaGetSymbolAddress((void**)&pv,    g_v);
    cudaGetSymbolAddress((void**)&pctx,  g_ctx);
    cudaGetSymbolAddress((void**)&ptmp,  g_tmp);
    cudaGetSymbolAddress((void**)&pwtF,  g_wtF);
    cudaGetSymbolAddress((void**)&pwtQ,  g_wtQ);
    cudaGetSymbolAddress((void**)&pwtK,  g_wtK);
    cudaGetSymbolAddress((void**)&pwtV,  g_wtV);
    cudaGetSymbolAddress((void**)&pwtO,  g_wtO);

    // ---- setup: bitmask hypergraph ----
    build_node_kernel<<<N_, 256>>>(H);
    bittrans_kernel<<<dim3(E_ / 32, N_ / 256), 256>>>();
    build_edge_kernel<<<E_, 128>>>();
    wtrans_all_kernel<<<dim3(NHID_ / 32, NHID_ / 32, 17), dim3(32, 8)>>>(w_feat, Wq, Wk, Wv, Wo);

    dim3 gemm_grid(NHID_ / 128, N_ / 64, 1);
    dim3 qkv_grid(NHID_ / 128, N_ / 64, 3);

    gemm_bf16_kernel<<<gemm_grid, 256>>>(X0, pwtF, pwtF, pwtF,
                                         px, px, px, b_feat, b_feat, b_feat, 0, 0, 0);

    for (int i = 0; i < NLAYER_; i++) {
        const __nv_bfloat16* WqT = pwtQ + (size_t)i * NHID_ * NHID_;
        const __nv_bfloat16* WkT = pwtK + (size_t)i * NHID_ * NHID_;
        const __nv_bfloat16* WvT = pwtV + (size_t)i * NHID_ * NHID_;
        const __nv_bfloat16* WoT = pwtO + (size_t)i * NHID_ * NHID_;
        const float* bqi = bq + (size_t)i * NHID_;
        const float* bki = bk + (size_t)i * NHID_;
        const float* bvi = bv + (size_t)i * NHID_;
        const float* boi = bo + (size_t)i * NHID_;

        gemm_bf16_kernel<<<qkv_grid, 256>>>(px, WqT, WkT, WvT, pq, pk, pv,
                                            bqi, bki, bvi, 1, 1, 2);

        attn_kernel<<<dim3(N_ / 128, NHEAD_), 256>>>();

        edge_gather_kernel<<<E_, 128>>>();
        node_scatter_kernel<<<N_, 128>>>();

        gemm_bf16_kernel<<<gemm_grid, 256>>>(pctx, WoT, WoT, WoT,
                                             ptmp, ptmp, ptmp, boi, boi, boi, 0, 0, 0);

        ln_prelu_kernel<<<N_ / 8, 256>>>(ln_g + (size_t)i * NHID_, ln_b + (size_t)i * NHID_,
                                         prelu_a, i);
    }

    cls_kernel<<<N_ / 8, 256>>>(w_cls, b_cls, out);
}

// round 16
// speedup vs baseline: 1.5440x; 1.5440x over previous
#include <cuda_runtime.h>
#include <cuda_bf16.h>
#include <math.h>

#define N_      4096
#define E_      4096
#define NHID_   512
#define NHEAD_  8
#define DK_     64
#define NLAYER_ 4
#define NCLASS_ 16
#define CAP_    256
#define L2E_    1.4426950408889634f

// ---------------- device scratch (static, no allocation) ----------------
__device__ float g_HT [(size_t)E_ * N_];
__device__ float g_U  [(size_t)E_ * NHID_];
__device__ float g_x  [N_ * NHID_];
__device__ __nv_bfloat16 g_q [N_ * NHID_];
__device__ __nv_bfloat16 g_k [N_ * NHID_];
__device__ float g_v  [N_ * NHID_];
__device__ __nv_bfloat16 g_vt[(size_t)NHEAD_ * DK_ * N_];
__device__ float g_ctx[N_ * NHID_];
__device__ float g_tmp[N_ * NHID_];
__device__ float g_dv2[N_];
__device__ float g_dei[E_];
__device__ int   g_adjN[(size_t)N_ * CAP_];
__device__ int   g_adjE[(size_t)E_ * CAP_];
__device__ int   g_degN[N_];
__device__ int   g_degE[E_];
__device__ __nv_bfloat16 g_wtF[NHID_ * NHID_];
__device__ __nv_bfloat16 g_wtQ[NLAYER_ * NHID_ * NHID_];
__device__ __nv_bfloat16 g_wtK[NLAYER_ * NHID_ * NHID_];
__device__ __nv_bfloat16 g_wtV[NLAYER_ * NHID_ * NHID_];
__device__ __nv_bfloat16 g_wtO[NLAYER_ * NHID_ * NHID_];

// ---------------- helpers ----------------
__device__ __forceinline__ void mma_bf16(
    float& d0, float& d1, float& d2, float& d3,
    unsigned a0, unsigned a1, unsigned a2, unsigned a3,
    unsigned b0, unsigned b1)
{
    asm volatile(
        "mma.sync.aligned.m16n8k16.row.col.f32.bf16.bf16.f32 "
        "{%0,%1,%2,%3}, {%4,%5,%6,%7}, {%8,%9}, {%0,%1,%2,%3};"
        : "+f"(d0), "+f"(d1), "+f"(d2), "+f"(d3)
        : "r"(a0), "r"(a1), "r"(a2), "r"(a3), "r"(b0), "r"(b1));
}
__device__ __forceinline__ void ldsm_x4(
    unsigned& r0, unsigned& r1, unsigned& r2, unsigned& r3, unsigned addr)
{
    asm volatile(
        "ldmatrix.sync.aligned.m8n8.x4.shared.b16 {%0,%1,%2,%3}, [%4];"
        : "=r"(r0), "=r"(r1), "=r"(r2), "=r"(r3) : "r"(addr));
}
__device__ __forceinline__ unsigned pack_bf16(float x, float y) {
    __nv_bfloat162 v = __floats2bfloat162_rn(x, y);
    return *(unsigned*)&v;
}
__device__ __forceinline__ uint4 pack8(float4 a, float4 b) {
    uint4 o;
    o.x = pack_bf16(a.x, a.y); o.y = pack_bf16(a.z, a.w);
    o.z = pack_bf16(b.x, b.y); o.w = pack_bf16(b.z, b.w);
    return o;
}
#define CP_ASYNC16(dst, src) \
    asm volatile("cp.async.ca.shared.global [%0], [%1], 16;" :: "r"(dst), "l"(src))
#define CP_COMMIT() asm volatile("cp.async.commit_group;")
#define CP_WAIT(n)  asm volatile("cp.async.wait_group %0;" :: "n"(n))

// ---------------- all weight transposes in one launch ----------------
__global__ void wtrans_all_kernel(const float* __restrict__ w_feat,
                                  const float* __restrict__ Wq, const float* __restrict__ Wk,
                                  const float* __restrict__ Wv, const float* __restrict__ Wo)
{
    __shared__ float tile[32][33];
    const int z = blockIdx.z;
    const float* W;
    __nv_bfloat16* out;
    if (z == 0) { W = w_feat; out = g_wtF; }
    else {
        int which = (z - 1) >> 2, layer = (z - 1) & 3;
        size_t off = (size_t)layer * NHID_ * NHID_;
        W   = (which == 0) ? Wq : (which == 1) ? Wk : (which == 2) ? Wv : Wo;
        out = (which == 0) ? g_wtQ : (which == 1) ? g_wtK : (which == 2) ? g_wtV : g_wtO;
        W += off; out += off;
    }
    int bx = blockIdx.x * 32, by = blockIdx.y * 32;
    int tx = threadIdx.x, ty = threadIdx.y;
    #pragma unroll
    for (int i = 0; i < 32; i += 8)
        tile[ty + i][tx] = W[(size_t)(by + ty + i) * NHID_ + bx + tx];
    __syncthreads();
    #pragma unroll
    for (int i = 0; i < 32; i += 8)
        out[(size_t)(bx + ty + i) * NHID_ + by + tx] = __float2bfloat16(tile[tx][ty + i]);
}

// ---------------- bf16 tensor-core GEMM (64x128, 256 thr) ----------------
__global__ __launch_bounds__(256, 2) void gemm_bf16_kernel(
    const float* __restrict__ A,
    const __nv_bfloat16* __restrict__ B0t, const __nv_bfloat16* __restrict__ B1t,
    const __nv_bfloat16* __restrict__ B2t,
    void* __restrict__ C0v, void* __restrict__ C1v, void* __restrict__ C2v,
    const float* __restrict__ bias0, const float* __restrict__ bias1, const float* __restrict__ bias2,
    int m0_, int m1_, int m2_)
{
    constexpr int BM = 64, BN = 128, BK = 32, KK = NHID_;
    constexpr int SW = 20;
    __shared__ __align__(16) unsigned As[2][BM][SW];
    __shared__ __align__(16) unsigned Bs[2][BN][SW];

    const int z = blockIdx.z;
    const __nv_bfloat16* Bt = (z == 0) ? B0t : (z == 1) ? B1t : B2t;
    void* Cv          = (z == 0) ? C0v : (z == 1) ? C1v : C2v;
    const float* bias = (z == 0) ? bias0 : (z == 1) ? bias1 : bias2;
    const int mode    = (z == 0) ? m0_ : (z == 1) ? m1_ : m2_;

    const int bm = blockIdx.y * BM, bn = blockIdx.x * BN;
    const int tid = threadIdx.x;
    const int lane = tid & 31, w = tid >> 5;
    const int g = lane >> 2, tg = lane & 3;
    const int m0w = (w & 1) * 32, n0w = (w >> 1) * 32;

    const int ar = tid >> 2, aw4 = (tid & 3) * 4;
    const int br = tid >> 1, bw4 = (tid & 1) * 8;
    const unsigned* Btw = (const unsigned*)Bt;

    float acc[2][4][4];
    #pragma unroll
    for (int mt = 0; mt < 2; mt++)
        #pragma unroll
        for (int nt = 0; nt < 4; nt++)
            #pragma unroll
            for (int j = 0; j < 4; j++) acc[mt][nt][j] = 0.f;

    {
        const float* ap = A + (size_t)(bm + ar) * KK + aw4 * 2;
        float4 a0 = *(const float4*)ap, a1 = *(const float4*)(ap + 4);
        *(uint4*)&As[0][ar][aw4] = pack8(a0, a1);
        const unsigned* bp = Btw + (size_t)(bn + br) * (KK / 2) + bw4;
        *(uint4*)&Bs[0][br][bw4]     = *(const uint4*)bp;
        *(uint4*)&Bs[0][br][bw4 + 4] = *(const uint4*)(bp + 4);
    }
    __syncthreads();

    const int nk = KK / BK;
    for (int t = 0; t < nk; t++) {
        float4 ra0, ra1;
        uint4 rb0, rb1;
        const bool pf = (t + 1 < nk);
        if (pf) {
            const int k0 = (t + 1) * BK;
            const float* ap = A + (size_t)(bm + ar) * KK + k0 + aw4 * 2;
            ra0 = *(const float4*)ap; ra1 = *(const float4*)(ap + 4);
            const unsigned* bp = Btw + (size_t)(bn + br) * (KK / 2) + k0 / 2 + bw4;
            rb0 = *(const uint4*)bp; rb1 = *(const uint4*)(bp + 4);
        }
        const int cur = t & 1;
        #pragma unroll
        for (int s = 0; s < 2; s++) {
            const int kb = s * 8;
            unsigned a[2][4], b[4][2];
            #pragma unroll
            for (int mt = 0; mt < 2; mt++) {
                const unsigned* r0 = &As[cur][m0w + mt * 16 + g][kb + tg];
                const unsigned* r1 = &As[cur][m0w + mt * 16 + g + 8][kb + tg];
                a[mt][0] = r0[0]; a[mt][1] = r1[0]; a[mt][2] = r0[4]; a[mt][3] = r1[4];
            }
            #pragma unroll
            for (int nt = 0; nt < 4; nt++) {
                const unsigned* rb = &Bs[cur][n0w + nt * 8 + g][kb + tg];
                b[nt][0] = rb[0]; b[nt][1] = rb[4];
            }
            #pragma unroll
            for (int mt = 0; mt < 2; mt++)
                #pragma unroll
                for (int nt = 0; nt < 4; nt++)
                    mma_bf16(acc[mt][nt][0], acc[mt][nt][1], acc[mt][nt][2], acc[mt][nt][3],
                             a[mt][0], a[mt][1], a[mt][2], a[mt][3], b[nt][0], b[nt][1]);
        }
        if (pf) {
            const int nxt = cur ^ 1;
            *(uint4*)&As[nxt][ar][aw4] = pack8(ra0, ra1);
            *(uint4*)&Bs[nxt][br][bw4]     = rb0;
            *(uint4*)&Bs[nxt][br][bw4 + 4] = rb1;
        }
        __syncthreads();
    }

    #pragma unroll
    for (int mt = 0; mt < 2; mt++) {
        const int r0 = bm + m0w + mt * 16 + g;
        #pragma unroll
        for (int nt = 0; nt < 4; nt++) {
            const int c = bn + n0w + nt * 8 + 2 * tg;
            float bx = __ldg(&bias[c]), by = __ldg(&bias[c + 1]);
            float v00 = acc[mt][nt][0] + bx, v01 = acc[mt][nt][1] + by;
            float v10 = acc[mt][nt][2] + bx, v11 = acc[mt][nt][3] + by;
            if (mode == 1) {
                __nv_bfloat16* Cb = (__nv_bfloat16*)Cv;
                *(__nv_bfloat162*)(Cb + (size_t)r0 * NHID_ + c) = __floats2bfloat162_rn(v00, v01);
                *(__nv_bfloat162*)(Cb + (size_t)(r0 + 8) * NHID_ + c) = __floats2bfloat162_rn(v10, v11);
            } else {
                float* C = (float*)Cv;
                *(float2*)(C + (size_t)r0 * NHID_ + c) = make_float2(v00, v01);
                *(float2*)(C + (size_t)(r0 + 8) * NHID_ + c) = make_float2(v10, v11);
                if (mode == 2) {
                    g_vt[(size_t)c * N_ + r0]           = __float2bfloat16(v00);
                    g_vt[(size_t)(c + 1) * N_ + r0]     = __float2bfloat16(v01);
                    g_vt[(size_t)c * N_ + r0 + 8]       = __float2bfloat16(v10);
                    g_vt[(size_t)(c + 1) * N_ + r0 + 8] = __float2bfloat16(v11);
                }
            }
        }
    }
}

// ---------------- FA bf16 flash attention (R12 + ldmatrix fragment loads) ----------------
__global__ __launch_bounds__(256, 2) void attn_kernel() {
    __shared__ __align__(16) unsigned Ks[2][64][36];
    __shared__ __align__(16) unsigned Vs[2][64][36];

    const int h = blockIdx.y, qb = blockIdx.x;
    const int tid = threadIdx.x, w = tid >> 5, lane = tid & 31;
    const int g = lane >> 2, tg = lane & 3;
    const int r0 = qb * 128 + w * 16 + g;
    const int lw = tid >> 3, lwd = (tid & 7) * 4, l4 = tid & 7;

    unsigned ks_dst[2][2], vs_dst[2][2];
    #pragma unroll
    for (int bufi = 0; bufi < 2; bufi++)
        #pragma unroll
        for (int i = 0; i < 2; i++) {
            int r = lw + i * 32;
            ks_dst[bufi][i] = (unsigned)__cvta_generic_to_shared(&Ks[bufi][r][lwd]);
            vs_dst[bufi][i] = (unsigned)__cvta_generic_to_shared(&Vs[bufi][r][lwd]);
        }

    // ldmatrix per-lane base: row = (lane&7) + ((lane>>4)&1)*8, col-words = ((lane>>3)&1)*4
    const int lmrow = (lane & 7) + ((lane >> 4) & 1) * 8;
    const int lmcol = ((lane >> 3) & 1) * 4;
    unsigned kfb[2], vfb[2];
    #pragma unroll
    for (int bufi = 0; bufi < 2; bufi++) {
        kfb[bufi] = (unsigned)__cvta_generic_to_shared(&Ks[bufi][lmrow][lmcol]);
        vfb[bufi] = (unsigned)__cvta_generic_to_shared(&Vs[bufi][lmrow][lmcol]);
    }

    unsigned qa[4][4];
    {
        const __nv_bfloat16* Q0 = g_q + (size_t)r0 * NHID_ + h * 64;
        const __nv_bfloat16* Q1 = Q0 + (size_t)8 * NHID_;
        const __nv_bfloat162 s2 = __floats2bfloat162_rn(0.125f, 0.125f);
        #pragma unroll
        for (int ks = 0; ks < 4; ks++) {
            __nv_bfloat162 t;
            t = __hmul2(*(const __nv_bfloat162*)(Q0 + ks * 16 + 2 * tg), s2);
            qa[ks][0] = *(unsigned*)&t;
            t = __hmul2(*(const __nv_bfloat162*)(Q1 + ks * 16 + 2 * tg), s2);
            qa[ks][1] = *(unsigned*)&t;
            t = __hmul2(*(const __nv_bfloat162*)(Q0 + ks * 16 + 8 + 2 * tg), s2);
            qa[ks][2] = *(unsigned*)&t;
            t = __hmul2(*(const __nv_bfloat162*)(Q1 + ks * 16 + 8 + 2 * tg), s2);
            qa[ks][3] = *(unsigned*)&t;
        }
    }

    float ol0 = 0.f, ol1 = 0.f;
    float oacc[8][4];
    #pragma unroll
    for (int nt = 0; nt < 8; nt++)
        #pragma unroll
        for (int j = 0; j < 4; j++) oacc[nt][j] = 0.f;

    #pragma unroll
    for (int i = 0; i < 2; i++) {
        int r = lw + i * 32;
        CP_ASYNC16(ks_dst[0][i], g_k + (size_t)r * NHID_ + h * 64 + l4 * 8);
        CP_ASYNC16(vs_dst[0][i], g_vt + ((size_t)h * 64 + r) * N_ + l4 * 8);
    }
    CP_COMMIT();

    for (int it = 0; it < N_ / 64; it++) {
        const int cur = it & 1;
        const bool pf = (it + 1 < N_ / 64);
        if (pf) {
            const int kvn = (it + 1) * 64;
            const int nxt = cur ^ 1;
            #pragma unroll
            for (int i = 0; i < 2; i++) {
                int r = lw + i * 32;
                CP_ASYNC16(ks_dst[nxt][i], g_k + (size_t)(kvn + r) * NHID_ + h * 64 + l4 * 8);
                CP_ASYNC16(vs_dst[nxt][i], g_vt + ((size_t)h * 64 + r) * N_ + kvn + l4 * 8);
            }
            CP_COMMIT();
            CP_WAIT(1);
        } else {
            CP_WAIT(0);
        }
        __syncthreads();

        // ---- S = Q @ K^T  (fragments via ldmatrix.x4, 2 n-tiles per load) ----
        float s[8][4];
        #pragma unroll
        for (int nt = 0; nt < 8; nt++)
            #pragma unroll
            for (int j = 0; j < 4; j++) s[nt][j] = 0.f;
        #pragma unroll
        for (int ks = 0; ks < 4; ks++) {
            #pragma unroll
            for (int p = 0; p < 4; p++) {
                unsigned b00, b01, b10, b11;
                ldsm_x4(b00, b01, b10, b11, kfb[cur] + (unsigned)((p * 576 + ks * 8) * 4));
                mma_bf16(s[2 * p][0], s[2 * p][1], s[2 * p][2], s[2 * p][3],
                         qa[ks][0], qa[ks][1], qa[ks][2], qa[ks][3], b00, b01);
                mma_bf16(s[2 * p + 1][0], s[2 * p + 1][1], s[2 * p + 1][2], s[2 * p + 1][3],
                         qa[ks][0], qa[ks][1], qa[ks][2], qa[ks][3], b10, b11);
            }
        }

        // ---- p = exp(S), partial sums, pack ----
        unsigned pw[8][2];
        #pragma unroll
        for (int nt = 0; nt < 8; nt++) {
            float p0 = exp2f(s[nt][0] * L2E_);
            float p1 = exp2f(s[nt][1] * L2E_);
            float p2 = exp2f(s[nt][2] * L2E_);
            float p3 = exp2f(s[nt][3] * L2E_);
            ol0 += p0 + p1; ol1 += p2 + p3;
            pw[nt][0] = pack_bf16(p0, p1);
            pw[nt][1] = pack_bf16(p2, p3);
        }

        // ---- O += P @ V  (fragments via ldmatrix.x4) ----
        #pragma unroll
        for (int kp = 0; kp < 4; kp++) {
            unsigned a0 = pw[2 * kp][0], a1 = pw[2 * kp][1];
            unsigned a2 = pw[2 * kp + 1][0], a3 = pw[2 * kp + 1][1];
            #pragma unroll
            for (int p = 0; p < 4; p++) {
                unsigned b00, b01, b10, b11;
                ldsm_x4(b00, b01, b10, b11, vfb[cur] + (unsigned)((p * 576 + kp * 8) * 4));
                mma_bf16(oacc[2 * p][0], oacc[2 * p][1], oacc[2 * p][2], oacc[2 * p][3],
                         a0, a1, a2, a3, b00, b01);
                mma_bf16(oacc[2 * p + 1][0], oacc[2 * p + 1][1], oacc[2 * p + 1][2], oacc[2 * p + 1][3],
                         a0, a1, a2, a3, b10, b11);
            }
        }
        __syncthreads();
    }

    ol0 += __shfl_xor_sync(0xffffffffu, ol0, 1);
    ol0 += __shfl_xor_sync(0xffffffffu, ol0, 2);
    ol1 += __shfl_xor_sync(0xffffffffu, ol1, 1);
    ol1 += __shfl_xor_sync(0xffffffffu, ol1, 2);

    float inv0 = 0.5f / ol0, inv1 = 0.5f / ol1;
    float* C0 = g_ctx + (size_t)r0 * NHID_ + h * 64;
    float* C1 = C0 + (size_t)8 * NHID_;
    #pragma unroll
    for (int nt = 0; nt < 8; nt++) {
        int c = nt * 8 + 2 * tg;
        *(float2*)(C0 + c) = make_float2(oacc[nt][0] * inv0, oacc[nt][1] * inv0);
        *(float2*)(C1 + c) = make_float2(oacc[nt][2] * inv1, oacc[nt][3] * inv1);
    }
}

// ---------------- transpose H -> HT ----------------
__global__ void transpose_kernel(const float* __restrict__ H) {
    __shared__ float tile[32][33];
    int bx = blockIdx.x * 32, by = blockIdx.y * 32;
    int tx = threadIdx.x, ty = threadIdx.y;
    #pragma unroll
    for (int i = 0; i < 32; i += 8)
        tile[ty + i][tx] = H[(size_t)(by + ty + i) * E_ + bx + tx];
    __syncthreads();
    #pragma unroll
    for (int i = 0; i < 32; i += 8)
        g_HT[(size_t)(bx + ty + i) * N_ + by + tx] = tile[tx][ty + i];
}

// ---------------- adjacency build ----------------
__global__ __launch_bounds__(256) void build_adj_kernel(
    const float* __restrict__ Mt, int cols, int* __restrict__ adj, int* __restrict__ deg,
    float* __restrict__ scl, int is_node)
{
    int row = blockIdx.x, tid = threadIdx.x;
    int w = tid >> 5, lane = tid & 31;
    const float* r = Mt + (size_t)row * cols;
    __shared__ int sc[128];

    #pragma unroll
    for (int i = 0; i < 16; i++) {
        int chunk = w * 16 + i;
        float v = r[chunk * 32 + lane];
        unsigned m = __ballot_sync(0xffffffffu, v != 0.f);
        if (lane == 0) sc[chunk] = __popc(m);
    }
    __syncthreads();

    for (int off = 1; off < 128; off <<= 1) {
        int v = (tid < 128 && tid >= off) ? sc[tid - off] : 0;
        __syncthreads();
        if (tid < 128) sc[tid] += v;
        __syncthreads();
    }

    #pragma unroll
    for (int i = 0; i < 16; i++) {
        int chunk = w * 16 + i;
        float v = r[chunk * 32 + lane];
        unsigned m = __ballot_sync(0xffffffffu, v != 0.f);
        int base = (chunk > 0) ? sc[chunk - 1] : 0;
        int rank = __popc(m & ((1u << lane) - 1u));
        if (v != 0.f && base + rank < CAP_)
            adj[(size_t)row * CAP_ + base + rank] = chunk * 32 + lane;
    }
    if (tid == 0) {
        int full = sc[127];
        deg[row] = min(full, CAP_);
        if (is_node) scl[row] = (row == 0) ? 1.0f : rsqrtf((float)full);
        else         scl[row] = 1.0f / (float)full;
    }
}

// ---------------- sparse G@V pieces ----------------
__global__ __launch_bounds__(128) void edge_gather_kernel() {
    int e = blockIdx.x, tid = threadIdx.x;
    int d = g_degE[e];
    const int* lst = g_adjE + (size_t)e * CAP_;
    float4 acc = make_float4(0.f, 0.f, 0.f, 0.f);
    const float4* V4 = (const float4*)g_v;
    for (int t = 0; t < d; t++) {
        int n = lst[t];
        float w = g_dv2[n];
        float4 v = V4[(size_t)n * (NHID_ / 4) + tid];
        acc.x += w * v.x; acc.y += w * v.y; acc.z += w * v.z; acc.w += w * v.w;
    }
    float de = g_dei[e];
    acc.x *= de; acc.y *= de; acc.z *= de; acc.w *= de;
    ((float4*)g_U)[(size_t)e * (NHID_ / 4) + tid] = acc;
}

__global__ __launch_bounds__(128) void node_scatter_kernel() {
    int n = blockIdx.x, tid = threadIdx.x;
    int d = g_degN[n];
    const int* lst = g_adjN + (size_t)n * CAP_;
    float4 acc = make_float4(0.f, 0.f, 0.f, 0.f);
    const float4* U4 = (const float4*)g_U;
    for (int t = 0; t < d; t++) {
        int e = lst[t];
        float4 u = U4[(size_t)e * (NHID_ / 4) + tid];
        acc.x += u.x; acc.y += u.y; acc.z += u.z; acc.w += u.w;
    }
    float w = 0.5f * g_dv2[n];
    float4* cp = (float4*)g_ctx + (size_t)n * (NHID_ / 4) + tid;
    float4 c = *cp;
    c.x += w * acc.x; c.y += w * acc.y; c.z += w * acc.z; c.w += w * acc.w;
    *cp = c;
}

// ---------------- layernorm + residual + PReLU: warp per row ----------------
__global__ __launch_bounds__(256) void ln_prelu_kernel(
    const float* __restrict__ g, const float* __restrict__ b,
    const float* __restrict__ prelu_a, int layer)
{
    const int w = threadIdx.x >> 5, lane = threadIdx.x & 31;
    const int n = blockIdx.x * 8 + w;
    const size_t base = (size_t)n * NHID_;
    float t[16];
    #pragma unroll
    for (int j = 0; j < 4; j++) {
        int c = j * 128 + lane * 4;
        float4 a = *(const float4*)(g_tmp + base + c);
        float4 x = *(const float4*)(g_x + base + c);
        t[j * 4 + 0] = a.x + x.x; t[j * 4 + 1] = a.y + x.y;
        t[j * 4 + 2] = a.z + x.z; t[j * 4 + 3] = a.w + x.w;
    }
    float s = 0.f;
    #pragma unroll
    for (int i = 0; i < 16; i++) s += t[i];
    #pragma unroll
    for (int o = 16; o > 0; o >>= 1) s += __shfl_xor_sync(0xffffffffu, s, o);
    float mu = s * (1.0f / NHID_);
    float vs = 0.f;
    #pragma unroll
    for (int i = 0; i < 16; i++) { float d = t[i] - mu; vs += d * d; }
    #pragma unroll
    for (int o = 16; o > 0; o >>= 1) vs += __shfl_xor_sync(0xffffffffu, vs, o);
    float rs = rsqrtf(vs * (1.0f / NHID_) + 1e-5f);
    float a = prelu_a[layer];
    #pragma unroll
    for (int j = 0; j < 4; j++) {
        int c = j * 128 + lane * 4;
        float4 gg = *(const float4*)(g + c);
        float4 bb = *(const float4*)(b + c);
        float4 y;
        y.x = (t[j * 4 + 0] - mu) * rs * gg.x + bb.x;
        y.y = (t[j * 4 + 1] - mu) * rs * gg.y + bb.y;
        y.z = (t[j * 4 + 2] - mu) * rs * gg.z + bb.z;
        y.w = (t[j * 4 + 3] - mu) * rs * gg.w + bb.w;
        y.x = (y.x >= 0.f) ? y.x : a * y.x;
        y.y = (y.y >= 0.f) ? y.y : a * y.y;
        y.z = (y.z >= 0.f) ? y.z : a * y.z;
        y.w = (y.w >= 0.f) ? y.w : a * y.w;
        *(float4*)(g_x + base + c) = y;
    }
}

// ---------------- classifier + log_softmax ----------------
__global__ __launch_bounds__(256) void cls_kernel(
    const float* __restrict__ w_cls, const float* __restrict__ b_cls,
    float* __restrict__ out)
{
    int w = threadIdx.x >> 5, lane = threadIdx.x & 31;
    int n = blockIdx.x * 8 + w;
    int half = lane >> 4, c = lane & 15;
    const float* xr = g_x + (size_t)n * NHID_;
    float acc = 0.f;
    #pragma unroll 4
    for (int kk = 0; kk < 256; kk++) {
        int k = half * 256 + kk;
        acc += xr[k] * __ldg(&w_cls[k * NCLASS_ + c]);
    }
    acc += __shfl_xor_sync(0xffffffffu, acc, 16);
    acc += __ldg(&b_cls[c]);
    float mx = acc;
    #pragma unroll
    for (int o = 1; o < 16; o <<= 1) mx = fmaxf(mx, __shfl_xor_sync(0xffffffffu, mx, o));
    float e = expf(acc - mx), s = e;
    #pragma unroll
    for (int o = 1; o < 16; o <<= 1) s += __shfl_xor_sync(0xffffffffu, s, o);
    if (lane < 16) out[(size_t)n * NCLASS_ + c] = acc - mx - logf(s);
}

// ---------------- host ----------------
extern "C" void kernel_launch(void* const* d_in, const int* in_sizes, int n_in,
                              void* d_out, int out_size) {
    const float* X0      = (const float*)d_in[0];
    const float* H       = (const float*)d_in[1];
    const float* w_feat  = (const float*)d_in[2];
    const float* b_feat  = (const float*)d_in[3];
    const float* Wq      = (const float*)d_in[4];
    const float* bq      = (const float*)d_in[5];
    const float* Wk      = (const float*)d_in[6];
    const float* bk      = (const float*)d_in[7];
    const float* Wv      = (const float*)d_in[8];
    const float* bv      = (const float*)d_in[9];
    const float* Wo      = (const float*)d_in[10];
    const float* bo      = (const float*)d_in[11];
    const float* ln_g    = (const float*)d_in[12];
    const float* ln_b    = (const float*)d_in[13];
    const float* prelu_a = (const float*)d_in[14];
    const float* w_cls   = (const float*)d_in[15];
    const float* b_cls   = (const float*)d_in[16];
    float* out = (float*)d_out;

    float *px, *pv, *pctx, *ptmp, *pHT, *pdv2, *pdei;
    void *pq, *pk;
    __nv_bfloat16 *pwtF, *pwtQ, *pwtK, *pwtV, *pwtO;
    int *padjN, *padjE, *pdegN, *pdegE;
    cudaGetSymbolAddress((void**)&px,    g_x);
    cudaGetSymbolAddress(&pq,            g_q);
    cudaGetSymbolAddress(&pk,            g_k);
    cudaGetSymbolAddress((void**)&pv,    g_v);
    cudaGetSymbolAddress((void**)&pctx,  g_ctx);
    cudaGetSymbolAddress((void**)&ptmp,  g_tmp);
    cudaGetSymbolAddress((void**)&pHT,   g_HT);
    cudaGetSymbolAddress((void**)&pdv2,  g_dv2);
    cudaGetSymbolAddress((void**)&pdei,  g_dei);
    cudaGetSymbolAddress((void**)&pwtF,  g_wtF);
    cudaGetSymbolAddress((void**)&pwtQ,  g_wtQ);
    cudaGetSymbolAddress((void**)&pwtK,  g_wtK);
    cudaGetSymbolAddress((void**)&pwtV,  g_wtV);
    cudaGetSymbolAddress((void**)&pwtO,  g_wtO);
    cudaGetSymbolAddress((void**)&padjN, g_adjN);
    cudaGetSymbolAddress((void**)&padjE, g_adjE);
    cudaGetSymbolAddress((void**)&pdegN, g_degN);
    cudaGetSymbolAddress((void**)&pdegE, g_degE);

    // ---- setup ----
    transpose_kernel<<<dim3(E_ / 32, N_ / 32), dim3(32, 8)>>>(H);
    build_adj_kernel<<<N_, 256>>>(H, E_, padjN, pdegN, pdv2, 1);
    build_adj_kernel<<<E_, 256>>>(pHT, N_, padjE, pdegE, pdei, 0);
    wtrans_all_kernel<<<dim3(NHID_ / 32, NHID_ / 32, 17), dim3(32, 8)>>>(w_feat, Wq, Wk, Wv, Wo);

    dim3 gemm_grid(NHID_ / 128, N_ / 64, 1);
    dim3 qkv_grid(NHID_ / 128, N_ / 64, 3);

    gemm_bf16_kernel<<<gemm_grid, 256>>>(X0, pwtF, pwtF, pwtF,
                                         px, px, px, b_feat, b_feat, b_feat, 0, 0, 0);

    for (int i = 0; i < NLAYER_; i++) {
        const __nv_bfloat16* WqT = pwtQ + (size_t)i * NHID_ * NHID_;
        const __nv_bfloat16* WkT = pwtK + (size_t)i * NHID_ * NHID_;
        const __nv_bfloat16* WvT = pwtV + (size_t)i * NHID_ * NHID_;
        const __nv_bfloat16* WoT = pwtO + (size_t)i * NHID_ * NHID_;
        const float* bqi = bq + (size_t)i * NHID_;
        const float* bki = bk + (size_t)i * NHID_;
        const float* bvi = bv + (size_t)i * NHID_;
        const float* boi = bo + (size_t)i * NHID_;

        gemm_bf16_kernel<<<qkv_grid, 256>>>(px, WqT, WkT, WvT, pq, pk, pv,
                                            bqi, bki, bvi, 1, 1, 2);

        attn_kernel<<<dim3(N_ / 128, NHEAD_), 256>>>();

        edge_gather_kernel<<<E_, 128>>>();
        node_scatter_kernel<<<N_, 128>>>();

        gemm_bf16_kernel<<<gemm_grid, 256>>>(pctx, WoT, WoT, WoT,
                                             ptmp, ptmp, ptmp, boi, boi, boi, 0, 0, 0);

        ln_prelu_kernel<<<N_ / 8, 256>>>(ln_g + (size_t)i * NHID_, ln_b + (size_t)i * NHID_,
                                         prelu_a, i);
    }

    cls_kernel<<<N_ / 8, 256>>>(w_cls, b_cls, out);
}

// round 17
// speedup vs baseline: 1.5742x; 1.0196x over previous
#include <cuda_runtime.h>
#include <cuda_bf16.h>
#include <math.h>

#define N_      4096
#define E_      4096
#define NHID_   512
#define NHEAD_  8
#define DK_     64
#define NLAYER_ 4
#define NCLASS_ 16
#define CAP_    256
#define L2E_    1.4426950408889634f

// ---------------- device scratch (static, no allocation) ----------------
__device__ float g_HT [(size_t)E_ * N_];
__device__ float g_U  [(size_t)E_ * NHID_];
__device__ float g_x  [N_ * NHID_];
__device__ __nv_bfloat16 g_q [N_ * NHID_];
__device__ __nv_bfloat16 g_k [N_ * NHID_];
__device__ float g_v  [N_ * NHID_];
__device__ __nv_bfloat16 g_vt[(size_t)NHEAD_ * DK_ * N_];
__device__ float g_ctx[N_ * NHID_];
__device__ float g_tmp[N_ * NHID_];
__device__ float g_dv2[N_];
__device__ float g_dei[E_];
__device__ int   g_adjN[(size_t)N_ * CAP_];
__device__ int   g_adjE[(size_t)E_ * CAP_];
__device__ int   g_degN[N_];
__device__ int   g_degE[E_];
__device__ __nv_bfloat16 g_wtF[NHID_ * NHID_];
__device__ __nv_bfloat16 g_wtQ[NLAYER_ * NHID_ * NHID_];
__device__ __nv_bfloat16 g_wtK[NLAYER_ * NHID_ * NHID_];
__device__ __nv_bfloat16 g_wtV[NLAYER_ * NHID_ * NHID_];
__device__ __nv_bfloat16 g_wtO[NLAYER_ * NHID_ * NHID_];

// ---------------- helpers ----------------
__device__ __forceinline__ void mma_bf16(
    float& d0, float& d1, float& d2, float& d3,
    unsigned a0, unsigned a1, unsigned a2, unsigned a3,
    unsigned b0, unsigned b1)
{
    asm volatile(
        "mma.sync.aligned.m16n8k16.row.col.f32.bf16.bf16.f32 "
        "{%0,%1,%2,%3}, {%4,%5,%6,%7}, {%8,%9}, {%0,%1,%2,%3};"
        : "+f"(d0), "+f"(d1), "+f"(d2), "+f"(d3)
        : "r"(a0), "r"(a1), "r"(a2), "r"(a3), "r"(b0), "r"(b1));
}
__device__ __forceinline__ void ldsm_x4(
    unsigned& r0, unsigned& r1, unsigned& r2, unsigned& r3, unsigned addr)
{
    asm volatile(
        "ldmatrix.sync.aligned.m8n8.x4.shared.b16 {%0,%1,%2,%3}, [%4];"
        : "=r"(r0), "=r"(r1), "=r"(r2), "=r"(r3) : "r"(addr));
}
__device__ __forceinline__ unsigned pack_bf16(float x, float y) {
    __nv_bfloat162 v = __floats2bfloat162_rn(x, y);
    return *(unsigned*)&v;
}
__device__ __forceinline__ uint4 pack8(float4 a, float4 b) {
    uint4 o;
    o.x = pack_bf16(a.x, a.y); o.y = pack_bf16(a.z, a.w);
    o.z = pack_bf16(b.x, b.y); o.w = pack_bf16(b.z, b.w);
    return o;
}
#define CP_ASYNC16(dst, src) \
    asm volatile("cp.async.ca.shared.global [%0], [%1], 16;" :: "r"(dst), "l"(src))
#define CP_COMMIT() asm volatile("cp.async.commit_group;")
#define CP_WAIT(n)  asm volatile("cp.async.wait_group %0;" :: "n"(n))

// ---------------- all weight transposes in one launch ----------------
__global__ void wtrans_all_kernel(const float* __restrict__ w_feat,
                                  const float* __restrict__ Wq, const float* __restrict__ Wk,
                                  const float* __restrict__ Wv, const float* __restrict__ Wo)
{
    __shared__ float tile[32][33];
    const int z = blockIdx.z;
    const float* W;
    __nv_bfloat16* out;
    if (z == 0) { W = w_feat; out = g_wtF; }
    else {
        int which = (z - 1) >> 2, layer = (z - 1) & 3;
        size_t off = (size_t)layer * NHID_ * NHID_;
        W   = (which == 0) ? Wq : (which == 1) ? Wk : (which == 2) ? Wv : Wo;
        out = (which == 0) ? g_wtQ : (which == 1) ? g_wtK : (which == 2) ? g_wtV : g_wtO;
        W += off; out += off;
    }
    int bx = blockIdx.x * 32, by = blockIdx.y * 32;
    int tx = threadIdx.x, ty = threadIdx.y;
    #pragma unroll
    for (int i = 0; i < 32; i += 8)
        tile[ty + i][tx] = W[(size_t)(by + ty + i) * NHID_ + bx + tx];
    __syncthreads();
    #pragma unroll
    for (int i = 0; i < 32; i += 8)
        out[(size_t)(bx + ty + i) * NHID_ + by + tx] = __float2bfloat16(tile[tx][ty + i]);
}

// ---------------- bf16 tensor-core GEMM (64x128, 256 thr, ldmatrix fragments) ----------------
__global__ __launch_bounds__(256, 2) void gemm_bf16_kernel(
    const float* __restrict__ A,
    const __nv_bfloat16* __restrict__ B0t, const __nv_bfloat16* __restrict__ B1t,
    const __nv_bfloat16* __restrict__ B2t,
    void* __restrict__ C0v, void* __restrict__ C1v, void* __restrict__ C2v,
    const float* __restrict__ bias0, const float* __restrict__ bias1, const float* __restrict__ bias2,
    int m0_, int m1_, int m2_)
{
    constexpr int BM = 64, BN = 128, BK = 32, KK = NHID_;
    constexpr int SW = 20;
    __shared__ __align__(16) unsigned As[2][BM][SW];
    __shared__ __align__(16) unsigned Bs[2][BN][SW];

    const int z = blockIdx.z;
    const __nv_bfloat16* Bt = (z == 0) ? B0t : (z == 1) ? B1t : B2t;
    void* Cv          = (z == 0) ? C0v : (z == 1) ? C1v : C2v;
    const float* bias = (z == 0) ? bias0 : (z == 1) ? bias1 : bias2;
    const int mode    = (z == 0) ? m0_ : (z == 1) ? m1_ : m2_;

    const int bm = blockIdx.y * BM, bn = blockIdx.x * BN;
    const int tid = threadIdx.x;
    const int lane = tid & 31, w = tid >> 5;
    const int g = lane >> 2, tg = lane & 3;
    const int m0w = (w & 1) * 32, n0w = (w >> 1) * 32;

    const int ar = tid >> 2, aw4 = (tid & 3) * 4;
    const int br = tid >> 1, bw4 = (tid & 1) * 8;
    const unsigned* Btw = (const unsigned*)Bt;

    // ldmatrix lane maps (bit-exact with prior scalar fragment layout)
    const int a_row = m0w + (lane & 7) + ((lane >> 3) & 1) * 8;   // + mt*16
    const int a_clw = ((lane >> 4) & 1) * 4;                      // + kb
    const int b_row = n0w + (lane & 7) + ((lane >> 4) & 1) * 8;   // + p*16
    const int b_clw = ((lane >> 3) & 1) * 4;                      // + kb
    unsigned abase[2][2], bbase[2][2];
    #pragma unroll
    for (int bufi = 0; bufi < 2; bufi++) {
        #pragma unroll
        for (int mt = 0; mt < 2; mt++)
            abase[bufi][mt] = (unsigned)__cvta_generic_to_shared(&As[bufi][a_row + mt * 16][a_clw]);
        #pragma unroll
        for (int p = 0; p < 2; p++)
            bbase[bufi][p] = (unsigned)__cvta_generic_to_shared(&Bs[bufi][b_row + p * 16][b_clw]);
    }

    float acc[2][4][4];
    #pragma unroll
    for (int mt = 0; mt < 2; mt++)
        #pragma unroll
        for (int nt = 0; nt < 4; nt++)
            #pragma unroll
            for (int j = 0; j < 4; j++) acc[mt][nt][j] = 0.f;

    {
        const float* ap = A + (size_t)(bm + ar) * KK + aw4 * 2;
        float4 a0 = *(const float4*)ap, a1 = *(const float4*)(ap + 4);
        *(uint4*)&As[0][ar][aw4] = pack8(a0, a1);
        const unsigned* bp = Btw + (size_t)(bn + br) * (KK / 2) + bw4;
        *(uint4*)&Bs[0][br][bw4]     = *(const uint4*)bp;
        *(uint4*)&Bs[0][br][bw4 + 4] = *(const uint4*)(bp + 4);
    }
    __syncthreads();

    const int nk = KK / BK;
    for (int t = 0; t < nk; t++) {
        float4 ra0, ra1;
        uint4 rb0, rb1;
        const bool pf = (t + 1 < nk);
        if (pf) {
            const int k0 = (t + 1) * BK;
            const float* ap = A + (size_t)(bm + ar) * KK + k0 + aw4 * 2;
            ra0 = *(const float4*)ap; ra1 = *(const float4*)(ap + 4);
            const unsigned* bp = Btw + (size_t)(bn + br) * (KK / 2) + k0 / 2 + bw4;
            rb0 = *(const uint4*)bp; rb1 = *(const uint4*)(bp + 4);
        }
        const int cur = t & 1;
        #pragma unroll
        for (int s = 0; s < 2; s++) {
            const unsigned kboff = (unsigned)(s * 8 * 4);   // bytes
            unsigned a[2][4], b[4][2];
            ldsm_x4(a[0][0], a[0][1], a[0][2], a[0][3], abase[cur][0] + kboff);
            ldsm_x4(a[1][0], a[1][1], a[1][2], a[1][3], abase[cur][1] + kboff);
            ldsm_x4(b[0][0], b[0][1], b[1][0], b[1][1], bbase[cur][0] + kboff);
            ldsm_x4(b[2][0], b[2][1], b[3][0], b[3][1], bbase[cur][1] + kboff);
            #pragma unroll
            for (int mt = 0; mt < 2; mt++)
                #pragma unroll
                for (int nt = 0; nt < 4; nt++)
                    mma_bf16(acc[mt][nt][0], acc[mt][nt][1], acc[mt][nt][2], acc[mt][nt][3],
                             a[mt][0], a[mt][1], a[mt][2], a[mt][3], b[nt][0], b[nt][1]);
        }
        if (pf) {
            const int nxt = cur ^ 1;
            *(uint4*)&As[nxt][ar][aw4] = pack8(ra0, ra1);
            *(uint4*)&Bs[nxt][br][bw4]     = rb0;
            *(uint4*)&Bs[nxt][br][bw4 + 4] = rb1;
        }
        __syncthreads();
    }

    #pragma unroll
    for (int mt = 0; mt < 2; mt++) {
        const int r0 = bm + m0w + mt * 16 + g;
        #pragma unroll
        for (int nt = 0; nt < 4; nt++) {
            const int c = bn + n0w + nt * 8 + 2 * tg;
            float bx = __ldg(&bias[c]), by = __ldg(&bias[c + 1]);
            float v00 = acc[mt][nt][0] + bx, v01 = acc[mt][nt][1] + by;
            float v10 = acc[mt][nt][2] + bx, v11 = acc[mt][nt][3] + by;
            if (mode == 1) {
                __nv_bfloat16* Cb = (__nv_bfloat16*)Cv;
                *(__nv_bfloat162*)(Cb + (size_t)r0 * NHID_ + c) = __floats2bfloat162_rn(v00, v01);
                *(__nv_bfloat162*)(Cb + (size_t)(r0 + 8) * NHID_ + c) = __floats2bfloat162_rn(v10, v11);
            } else {
                float* C = (float*)Cv;
                *(float2*)(C + (size_t)r0 * NHID_ + c) = make_float2(v00, v01);
                *(float2*)(C + (size_t)(r0 + 8) * NHID_ + c) = make_float2(v10, v11);
                if (mode == 2) {
                    g_vt[(size_t)c * N_ + r0]           = __float2bfloat16(v00);
                    g_vt[(size_t)(c + 1) * N_ + r0]     = __float2bfloat16(v01);
                    g_vt[(size_t)c * N_ + r0 + 8]       = __float2bfloat16(v10);
                    g_vt[(size_t)(c + 1) * N_ + r0 + 8] = __float2bfloat16(v11);
                }
            }
        }
    }
}

// ---------------- FA bf16 flash attention (R16: ldmatrix fragment loads) ----------------
__global__ __launch_bounds__(256, 2) void attn_kernel() {
    __shared__ __align__(16) unsigned Ks[2][64][36];
    __shared__ __align__(16) unsigned Vs[2][64][36];

    const int h = blockIdx.y, qb = blockIdx.x;
    const int tid = threadIdx.x, w = tid >> 5, lane = tid & 31;
    const int g = lane >> 2, tg = lane & 3;
    const int r0 = qb * 128 + w * 16 + g;
    const int lw = tid >> 3, lwd = (tid & 7) * 4, l4 = tid & 7;

    unsigned ks_dst[2][2], vs_dst[2][2];
    #pragma unroll
    for (int bufi = 0; bufi < 2; bufi++)
        #pragma unroll
        for (int i = 0; i < 2; i++) {
            int r = lw + i * 32;
            ks_dst[bufi][i] = (unsigned)__cvta_generic_to_shared(&Ks[bufi][r][lwd]);
            vs_dst[bufi][i] = (unsigned)__cvta_generic_to_shared(&Vs[bufi][r][lwd]);
        }

    const int lmrow = (lane & 7) + ((lane >> 4) & 1) * 8;
    const int lmcol = ((lane >> 3) & 1) * 4;
    unsigned kfb[2], vfb[2];
    #pragma unroll
    for (int bufi = 0; bufi < 2; bufi++) {
        kfb[bufi] = (unsigned)__cvta_generic_to_shared(&Ks[bufi][lmrow][lmcol]);
        vfb[bufi] = (unsigned)__cvta_generic_to_shared(&Vs[bufi][lmrow][lmcol]);
    }

    unsigned qa[4][4];
    {
        const __nv_bfloat16* Q0 = g_q + (size_t)r0 * NHID_ + h * 64;
        const __nv_bfloat16* Q1 = Q0 + (size_t)8 * NHID_;
        const __nv_bfloat162 s2 = __floats2bfloat162_rn(0.125f, 0.125f);
        #pragma unroll
        for (int ks = 0; ks < 4; ks++) {
            __nv_bfloat162 t;
            t = __hmul2(*(const __nv_bfloat162*)(Q0 + ks * 16 + 2 * tg), s2);
            qa[ks][0] = *(unsigned*)&t;
            t = __hmul2(*(const __nv_bfloat162*)(Q1 + ks * 16 + 2 * tg), s2);
            qa[ks][1] = *(unsigned*)&t;
            t = __hmul2(*(const __nv_bfloat162*)(Q0 + ks * 16 + 8 + 2 * tg), s2);
            qa[ks][2] = *(unsigned*)&t;
            t = __hmul2(*(const __nv_bfloat162*)(Q1 + ks * 16 + 8 + 2 * tg), s2);
            qa[ks][3] = *(unsigned*)&t;
        }
    }

    float ol0 = 0.f, ol1 = 0.f;
    float oacc[8][4];
    #pragma unroll
    for (int nt = 0; nt < 8; nt++)
        #pragma unroll
        for (int j = 0; j < 4; j++) oacc[nt][j] = 0.f;

    #pragma unroll
    for (int i = 0; i < 2; i++) {
        int r = lw + i * 32;
        CP_ASYNC16(ks_dst[0][i], g_k + (size_t)r * NHID_ + h * 64 + l4 * 8);
        CP_ASYNC16(vs_dst[0][i], g_vt + ((size_t)h * 64 + r) * N_ + l4 * 8);
    }
    CP_COMMIT();

    for (int it = 0; it < N_ / 64; it++) {
        const int cur = it & 1;
        const bool pf = (it + 1 < N_ / 64);
        if (pf) {
            const int kvn = (it + 1) * 64;
            const int nxt = cur ^ 1;
            #pragma unroll
            for (int i = 0; i < 2; i++) {
                int r = lw + i * 32;
                CP_ASYNC16(ks_dst[nxt][i], g_k + (size_t)(kvn + r) * NHID_ + h * 64 + l4 * 8);
                CP_ASYNC16(vs_dst[nxt][i], g_vt + ((size_t)h * 64 + r) * N_ + kvn + l4 * 8);
            }
            CP_COMMIT();
            CP_WAIT(1);
        } else {
            CP_WAIT(0);
        }
        __syncthreads();

        float s[8][4];
        #pragma unroll
        for (int nt = 0; nt < 8; nt++)
            #pragma unroll
            for (int j = 0; j < 4; j++) s[nt][j] = 0.f;
        #pragma unroll
        for (int ks = 0; ks < 4; ks++) {
            #pragma unroll
            for (int p = 0; p < 4; p++) {
                unsigned b00, b01, b10, b11;
                ldsm_x4(b00, b01, b10, b11, kfb[cur] + (unsigned)((p * 576 + ks * 8) * 4));
                mma_bf16(s[2 * p][0], s[2 * p][1], s[2 * p][2], s[2 * p][3],
                         qa[ks][0], qa[ks][1], qa[ks][2], qa[ks][3], b00, b01);
                mma_bf16(s[2 * p + 1][0], s[2 * p + 1][1], s[2 * p + 1][2], s[2 * p + 1][3],
                         qa[ks][0], qa[ks][1], qa[ks][2], qa[ks][3], b10, b11);
            }
        }

        unsigned pw[8][2];
        #pragma unroll
        for (int nt = 0; nt < 8; nt++) {
            float p0 = exp2f(s[nt][0] * L2E_);
            float p1 = exp2f(s[nt][1] * L2E_);
            float p2 = exp2f(s[nt][2] * L2E_);
            float p3 = exp2f(s[nt][3] * L2E_);
            ol0 += p0 + p1; ol1 += p2 + p3;
            pw[nt][0] = pack_bf16(p0, p1);
            pw[nt][1] = pack_bf16(p2, p3);
        }

        #pragma unroll
        for (int kp = 0; kp < 4; kp++) {
            unsigned a0 = pw[2 * kp][0], a1 = pw[2 * kp][1];
            unsigned a2 = pw[2 * kp + 1][0], a3 = pw[2 * kp + 1][1];
            #pragma unroll
            for (int p = 0; p < 4; p++) {
                unsigned b00, b01, b10, b11;
                ldsm_x4(b00, b01, b10, b11, vfb[cur] + (unsigned)((p * 576 + kp * 8) * 4));
                mma_bf16(oacc[2 * p][0], oacc[2 * p][1], oacc[2 * p][2], oacc[2 * p][3],
                         a0, a1, a2, a3, b00, b01);
                mma_bf16(oacc[2 * p + 1][0], oacc[2 * p + 1][1], oacc[2 * p + 1][2], oacc[2 * p + 1][3],
                         a0, a1, a2, a3, b10, b11);
            }
        }
        __syncthreads();
    }

    ol0 += __shfl_xor_sync(0xffffffffu, ol0, 1);
    ol0 += __shfl_xor_sync(0xffffffffu, ol0, 2);
    ol1 += __shfl_xor_sync(0xffffffffu, ol1, 1);
    ol1 += __shfl_xor_sync(0xffffffffu, ol1, 2);

    float inv0 = 0.5f / ol0, inv1 = 0.5f / ol1;
    float* C0 = g_ctx + (size_t)r0 * NHID_ + h * 64;
    float* C1 = C0 + (size_t)8 * NHID_;
    #pragma unroll
    for (int nt = 0; nt < 8; nt++) {
        int c = nt * 8 + 2 * tg;
        *(float2*)(C0 + c) = make_float2(oacc[nt][0] * inv0, oacc[nt][1] * inv0);
        *(float2*)(C1 + c) = make_float2(oacc[nt][2] * inv1, oacc[nt][3] * inv1);
    }
}

// ---------------- transpose H -> HT ----------------
__global__ void transpose_kernel(const float* __restrict__ H) {
    __shared__ float tile[32][33];
    int bx = blockIdx.x * 32, by = blockIdx.y * 32;
    int tx = threadIdx.x, ty = threadIdx.y;
    #pragma unroll
    for (int i = 0; i < 32; i += 8)
        tile[ty + i][tx] = H[(size_t)(by + ty + i) * E_ + bx + tx];
    __syncthreads();
    #pragma unroll
    for (int i = 0; i < 32; i += 8)
        g_HT[(size_t)(bx + ty + i) * N_ + by + tx] = tile[tx][ty + i];
}

// ---------------- adjacency build ----------------
__global__ __launch_bounds__(256) void build_adj_kernel(
    const float* __restrict__ Mt, int cols, int* __restrict__ adj, int* __restrict__ deg,
    float* __restrict__ scl, int is_node)
{
    int row = blockIdx.x, tid = threadIdx.x;
    int w = tid >> 5, lane = tid & 31;
    const float* r = Mt + (size_t)row * cols;
    __shared__ int sc[128];

    #pragma unroll
    for (int i = 0; i < 16; i++) {
        int chunk = w * 16 + i;
        float v = r[chunk * 32 + lane];
        unsigned m = __ballot_sync(0xffffffffu, v != 0.f);
        if (lane == 0) sc[chunk] = __popc(m);
    }
    __syncthreads();

    for (int off = 1; off < 128; off <<= 1) {
        int v = (tid < 128 && tid >= off) ? sc[tid - off] : 0;
        __syncthreads();
        if (tid < 128) sc[tid] += v;
        __syncthreads();
    }

    #pragma unroll
    for (int i = 0; i < 16; i++) {
        int chunk = w * 16 + i;
        float v = r[chunk * 32 + lane];
        unsigned m = __ballot_sync(0xffffffffu, v != 0.f);
        int base = (chunk > 0) ? sc[chunk - 1] : 0;
        int rank = __popc(m & ((1u << lane) - 1u));
        if (v != 0.f && base + rank < CAP_)
            adj[(size_t)row * CAP_ + base + rank] = chunk * 32 + lane;
    }
    if (tid == 0) {
        int full = sc[127];
        deg[row] = min(full, CAP_);
        if (is_node) scl[row] = (row == 0) ? 1.0f : rsqrtf((float)full);
        else         scl[row] = 1.0f / (float)full;
    }
}

// ---------------- sparse G@V pieces ----------------
__global__ __launch_bounds__(128) void edge_gather_kernel() {
    int e = blockIdx.x, tid = threadIdx.x;
    int d = g_degE[e];
    const int* lst = g_adjE + (size_t)e * CAP_;
    float4 acc = make_float4(0.f, 0.f, 0.f, 0.f);
    const float4* V4 = (const float4*)g_v;
    for (int t = 0; t < d; t++) {
        int n = lst[t];
        float w = g_dv2[n];
        float4 v = V4[(size_t)n * (NHID_ / 4) + tid];
        acc.x += w * v.x; acc.y += w * v.y; acc.z += w * v.z; acc.w += w * v.w;
    }
    float de = g_dei[e];
    acc.x *= de; acc.y *= de; acc.z *= de; acc.w *= de;
    ((float4*)g_U)[(size_t)e * (NHID_ / 4) + tid] = acc;
}

__global__ __launch_bounds__(128) void node_scatter_kernel() {
    int n = blockIdx.x, tid = threadIdx.x;
    int d = g_degN[n];
    const int* lst = g_adjN + (size_t)n * CAP_;
    float4 acc = make_float4(0.f, 0.f, 0.f, 0.f);
    const float4* U4 = (const float4*)g_U;
    for (int t = 0; t < d; t++) {
        int e = lst[t];
        float4 u = U4[(size_t)e * (NHID_ / 4) + tid];
        acc.x += u.x; acc.y += u.y; acc.z += u.z; acc.w += u.w;
    }
    float w = 0.5f * g_dv2[n];
    float4* cp = (float4*)g_ctx + (size_t)n * (NHID_ / 4) + tid;
    float4 c = *cp;
    c.x += w * acc.x; c.y += w * acc.y; c.z += w * acc.z; c.w += w * acc.w;
    *cp = c;
}

// ---------------- layernorm + residual + PReLU: warp per row ----------------
__global__ __launch_bounds__(256) void ln_prelu_kernel(
    const float* __restrict__ g, const float* __restrict__ b,
    const float* __restrict__ prelu_a, int layer)
{
    const int w = threadIdx.x >> 5, lane = threadIdx.x & 31;
    const int n = blockIdx.x * 8 + w;
    const size_t base = (size_t)n * NHID_;
    float t[16];
    #pragma unroll
    for (int j = 0; j < 4; j++) {
        int c = j * 128 + lane * 4;
        float4 a = *(const float4*)(g_tmp + base + c);
        float4 x = *(const float4*)(g_x + base + c);
        t[j * 4 + 0] = a.x + x.x; t[j * 4 + 1] = a.y + x.y;
        t[j * 4 + 2] = a.z + x.z; t[j * 4 + 3] = a.w + x.w;
    }
    float s = 0.f;
    #pragma unroll
    for (int i = 0; i < 16; i++) s += t[i];
    #pragma unroll
    for (int o = 16; o > 0; o >>= 1) s += __shfl_xor_sync(0xffffffffu, s, o);
    float mu = s * (1.0f / NHID_);
    float vs = 0.f;
    #pragma unroll
    for (int i = 0; i < 16; i++) { float d = t[i] - mu; vs += d * d; }
    #pragma unroll
    for (int o = 16; o > 0; o >>= 1) vs += __shfl_xor_sync(0xffffffffu, vs, o);
    float rs = rsqrtf(vs * (1.0f / NHID_) + 1e-5f);
    float a = prelu_a[layer];
    #pragma unroll
    for (int j = 0; j < 4; j++) {
        int c = j * 128 + lane * 4;
        float4 gg = *(const float4*)(g + c);
        float4 bb = *(const float4*)(b + c);
        float4 y;
        y.x = (t[j * 4 + 0] - mu) * rs * gg.x + bb.x;
        y.y = (t[j * 4 + 1] - mu) * rs * gg.y + bb.y;
        y.z = (t[j * 4 + 2] - mu) * rs * gg.z + bb.z;
        y.w = (t[j * 4 + 3] - mu) * rs * gg.w + bb.w;
        y.x = (y.x >= 0.f) ? y.x : a * y.x;
        y.y = (y.y >= 0.f) ? y.y : a * y.y;
        y.z = (y.z >= 0.f) ? y.z : a * y.z;
        y.w = (y.w >= 0.f) ? y.w : a * y.w;
        *(float4*)(g_x + base + c) = y;
    }
}

// ---------------- classifier + log_softmax ----------------
__global__ __launch_bounds__(256) void cls_kernel(
    const float* __restrict__ w_cls, const float* __restrict__ b_cls,
    float* __restrict__ out)
{
    int w = threadIdx.x >> 5, lane = threadIdx.x & 31;
    int n = blockIdx.x * 8 + w;
    int half = lane >> 4, c = lane & 15;
    const float* xr = g_x + (size_t)n * NHID_;
    float acc = 0.f;
    #pragma unroll 4
    for (int kk = 0; kk < 256; kk++) {
        int k = half * 256 + kk;
        acc += xr[k] * __ldg(&w_cls[k * NCLASS_ + c]);
    }
    acc += __shfl_xor_sync(0xffffffffu, acc, 16);
    acc += __ldg(&b_cls[c]);
    float mx = acc;
    #pragma unroll
    for (int o = 1; o < 16; o <<= 1) mx = fmaxf(mx, __shfl_xor_sync(0xffffffffu, mx, o));
    float e = expf(acc - mx), s = e;
    #pragma unroll
    for (int o = 1; o < 16; o <<= 1) s += __shfl_xor_sync(0xffffffffu, s, o);
    if (lane < 16) out[(size_t)n * NCLASS_ + c] = acc - mx - logf(s);
}

// ---------------- host ----------------
extern "C" void kernel_launch(void* const* d_in, const int* in_sizes, int n_in,
                              void* d_out, int out_size) {
    const float* X0      = (const float*)d_in[0];
    const float* H       = (const float*)d_in[1];
    const float* w_feat  = (const float*)d_in[2];
    const float* b_feat  = (const float*)d_in[3];
    const float* Wq      = (const float*)d_in[4];
    const float* bq      = (const float*)d_in[5];
    const float* Wk      = (const float*)d_in[6];
    const float* bk      = (const float*)d_in[7];
    const float* Wv      = (const float*)d_in[8];
    const float* bv      = (const float*)d_in[9];
    const float* Wo      = (const float*)d_in[10];
    const float* bo      = (const float*)d_in[11];
    const float* ln_g    = (const float*)d_in[12];
    const float* ln_b    = (const float*)d_in[13];
    const float* prelu_a = (const float*)d_in[14];
    const float* w_cls   = (const float*)d_in[15];
    const float* b_cls   = (const float*)d_in[16];
    float* out = (float*)d_out;

    float *px, *pv, *pctx, *ptmp, *pHT, *pdv2, *pdei;
    void *pq, *pk;
    __nv_bfloat16 *pwtF, *pwtQ, *pwtK, *pwtV, *pwtO;
    int *padjN, *padjE, *pdegN, *pdegE;
    cudaGetSymbolAddress((void**)&px,    g_x);
    cudaGetSymbolAddress(&pq,            g_q);
    cudaGetSymbolAddress(&pk,            g_k);
    cudaGetSymbolAddress((void**)&pv,    g_v);
    cudaGetSymbolAddress((void**)&pctx,  g_ctx);
    cudaGetSymbolAddress((void**)&ptmp,  g_tmp);
    cudaGetSymbolAddress((void**)&pHT,   g_HT);
    cudaGetSymbolAddress((void**)&pdv2,  g_dv2);
    cudaGetSymbolAddress((void**)&pdei,  g_dei);
    cudaGetSymbolAddress((void**)&pwtF,  g_wtF);
    cudaGetSymbolAddress((void**)&pwtQ,  g_wtQ);
    cudaGetSymbolAddress((void**)&pwtK,  g_wtK);
    cudaGetSymbolAddress((void**)&pwtV,  g_wtV);
    cudaGetSymbolAddress((void**)&pwtO,  g_wtO);
    cudaGetSymbolAddress((void**)&padjN, g_adjN);
    cudaGetSymbolAddress((void**)&padjE, g_adjE);
    cudaGetSymbolAddress((void**)&pdegN, g_degN);
    cudaGetSymbolAddress((void**)&pdegE, g_degE);

    // ---- setup ----
    transpose_kernel<<<dim3(E_ / 32, N_ / 32), dim3(32, 8)>>>(H);
    build_adj_kernel<<<N_, 256>>>(H, E_, padjN, pdegN, pdv2, 1);
    build_adj_kernel<<<E_, 256>>>(pHT, N_, padjE, pdegE, pdei, 0);
    wtrans_all_kernel<<<dim3(NHID_ / 32, NHID_ / 32, 17), dim3(32, 8)>>>(w_feat, Wq, Wk, Wv, Wo);

    dim3 gemm_grid(NHID_ / 128, N_ / 64, 1);
    dim3 qkv_grid(NHID_ / 128, N_ / 64, 3);

    gemm_bf16_kernel<<<gemm_grid, 256>>>(X0, pwtF, pwtF, pwtF,
                                         px, px, px, b_feat, b_feat, b_feat, 0, 0, 0);

    for (int i = 0; i < NLAYER_; i++) {
        const __nv_bfloat16* WqT = pwtQ + (size_t)i * NHID_ * NHID_;
        const __nv_bfloat16* WkT = pwtK + (size_t)i * NHID_ * NHID_;
        const __nv_bfloat16* WvT = pwtV + (size_t)i * NHID_ * NHID_;
        const __nv_bfloat16* WoT = pwtO + (size_t)i * NHID_ * NHID_;
        const float* bqi = bq + (size_t)i * NHID_;
        const float* bki = bk + (size_t)i * NHID_;
        const float* bvi = bv + (size_t)i * NHID_;
        const float* boi = bo + (size_t)i * NHID_;

        gemm_bf16_kernel<<<qkv_grid, 256>>>(px, WqT, WkT, WvT, pq, pk, pv,
                                            bqi, bki, bvi, 1, 1, 2);

        attn_kernel<<<dim3(N_ / 128, NHEAD_), 256>>>();

        edge_gather_kernel<<<E_, 128>>>();
        node_scatter_kernel<<<N_, 128>>>();

        gemm_bf16_kernel<<<gemm_grid, 256>>>(pctx, WoT, WoT, WoT,
                                             ptmp, ptmp, ptmp, boi, boi, boi, 0, 0, 0);

        ln_prelu_kernel<<<N_ / 8, 256>>>(ln_g + (size_t)i * NHID_, ln_b + (size_t)i * NHID_,
                                         prelu_a, i);
    }

    cls_kernel<<<N_ / 8, 256>>>(w_cls, b_cls, out);
}